// round 17
// baseline (speedup 1.0000x reference)
#include <cuda_runtime.h>
#include <cuda_bf16.h>
#include <cstdint>
#include <cmath>

#define BATCH 4
#define SEQ   2048
#define EMB   1024
#define HEADS 16
#define HDIM  64
#define MROWS (BATCH*SEQ)   // 8192
#define KPAIRS (EMB/2)      // 512

// Scratch (no allocations allowed)
__device__ float g_q[BATCH*HEADS*SEQ*HDIM];
__device__ float g_k[BATCH*HEADS*SEQ*HDIM];
__device__ float g_v[BATCH*HEADS*SEQ*HDIM];
// pre-split bf16 hi/lo planes (packed pairs as u32)
// A planes: [m][group of 8 pos p], p = 2*(kp&3) + (kp>>2)
__device__ uint32_t g_xh[MROWS*KPAIRS],  g_xl[MROWS*KPAIRS];
__device__ uint32_t g_aoh[MROWS*KPAIRS], g_aol[MROWS*KPAIRS];
// W planes: word index = ((slab*4 + kappa)*EMB + n)*2 + delta, kp = slab*8 + delta*4 + kappa
__device__ uint32_t g_wh[4*KPAIRS*EMB],  g_wl[4*KPAIRS*EMB];

// ---------------------------------------------------------------------------
// helpers
// ---------------------------------------------------------------------------
__device__ __forceinline__ uint32_t tf32_rna(float x) {
    uint32_t r;
    asm("cvt.rna.tf32.f32 %0, %1;" : "=r"(r) : "f"(x));
    return r;
}
__device__ __forceinline__ float4 cvt4(float4 v) {
    v.x = __uint_as_float(tf32_rna(v.x));
    v.y = __uint_as_float(tf32_rna(v.y));
    v.z = __uint_as_float(tf32_rna(v.z));
    v.w = __uint_as_float(tf32_rna(v.w));
    return v;
}
__device__ __forceinline__ void mma_tf32(float* c, const uint32_t* a, const uint32_t* b) {
    asm volatile(
        "mma.sync.aligned.m16n8k8.row.col.f32.tf32.tf32.f32 "
        "{%0,%1,%2,%3}, {%4,%5,%6,%7}, {%8,%9}, {%0,%1,%2,%3};"
        : "+f"(c[0]), "+f"(c[1]), "+f"(c[2]), "+f"(c[3])
        : "r"(a[0]), "r"(a[1]), "r"(a[2]), "r"(a[3]), "r"(b[0]), "r"(b[1]));
}
__device__ __forceinline__ void mma_bf16(float* c, const uint32_t* a, const uint32_t* b) {
    asm volatile(
        "mma.sync.aligned.m16n8k16.row.col.f32.bf16.bf16.f32 "
        "{%0,%1,%2,%3}, {%4,%5,%6,%7}, {%8,%9}, {%0,%1,%2,%3};"
        : "+f"(c[0]), "+f"(c[1]), "+f"(c[2]), "+f"(c[3])
        : "r"(a[0]), "r"(a[1]), "r"(a[2]), "r"(a[3]), "r"(b[0]), "r"(b[1]));
}
__device__ __forceinline__ void bf16split2(float x0, float x1, uint32_t& hi, uint32_t& lo) {
    __nv_bfloat16 h0 = __float2bfloat16_rn(x0);
    __nv_bfloat16 h1 = __float2bfloat16_rn(x1);
    float r0 = x0 - __bfloat162float(h0);
    float r1 = x1 - __bfloat162float(h1);
    __nv_bfloat16 l0 = __float2bfloat16_rn(r0);
    __nv_bfloat16 l1 = __float2bfloat16_rn(r1);
    hi = ((uint32_t)__bfloat16_as_ushort(h1) << 16) | (uint32_t)__bfloat16_as_ushort(h0);
    lo = ((uint32_t)__bfloat16_as_ushort(l1) << 16) | (uint32_t)__bfloat16_as_ushort(l0);
}

// ---------------------------------------------------------------------------
// pre-split kernels (emit the fragment-friendly layouts)
// ---------------------------------------------------------------------------
// x -> A planes, permuted within each 8-pair group: out[r][g*8+p] = pair(kp = g*8 + (p&1)*4 + (p>>1))
__global__ __launch_bounds__(256)
void split_pairs(const float* __restrict__ src, uint32_t* __restrict__ hp,
                 uint32_t* __restrict__ lp, int n_pairs)
{
    int i = blockIdx.x * blockDim.x + threadIdx.x;
    if (i >= n_pairs) return;
    const int r = i >> 9;
    const int pos = i & 511;
    const int g = pos >> 3, p = pos & 7;
    const int kp = g * 8 + (p & 1) * 4 + (p >> 1);
    const float2 v = ((const float2*)src)[(size_t)r * KPAIRS + kp];
    uint32_t h, l;
    bf16split2(v.x, v.y, h, l);
    hp[i] = h; lp[i] = l;
}

// W -> interleaved planes: word i: delta=i&1, n=(i>>1)&1023, kappa=(i>>11)&3, slab=i>>13
__global__ __launch_bounds__(256)
void split_w(const float* __restrict__ W0, const float* __restrict__ W1,
             const float* __restrict__ W2, const float* __restrict__ W3,
             uint32_t* __restrict__ hp, uint32_t* __restrict__ lp)
{
    const int z = blockIdx.y;
    const float* W = (z == 0) ? W0 : (z == 1) ? W1 : (z == 2) ? W2 : W3;
    int i = blockIdx.x * blockDim.x + threadIdx.x;
    const int dlt  = i & 1;
    const int n    = (i >> 1) & (EMB - 1);
    const int kap  = (i >> 11) & 3;
    const int slab = i >> 13;
    const int kp = slab * 8 + dlt * 4 + kap;
    const float a = W[((size_t)(2*kp))   * EMB + n];
    const float b = W[((size_t)(2*kp+1)) * EMB + n];
    uint32_t h, l;
    bf16split2(a, b, h, l);
    hp[(size_t)z * KPAIRS * EMB + i] = h;
    lp[(size_t)z * KPAIRS * EMB + i] = l;
}

// ---------------------------------------------------------------------------
// 3xBF16 GEMM body, LDS.64 fragment loads. Tile 128x128x16, 256 thr, 8 warps.
// SMEM (u32): A [row 128][8 pos] stride 12 (hi,lo);
//             B [kappa 4][264] (cols*2+delta) (hi,lo)
// ---------------------------------------------------------------------------
#define GSTG 5184
#define SAh(st,r,p)  smu[(st)*GSTG          + (r)*12  + (p)]
#define SAl(st,r,p)  smu[(st)*GSTG + 1536   + (r)*12  + (p)]
#define SBh2(st,k,w) smu[(st)*GSTG + 3072   + (k)*264 + (w)]
#define SBl2(st,k,w) smu[(st)*GSTG + 4128   + (k)*264 + (w)]
#define GEMM_SMEM_BYTES (2*GSTG*4)

__device__ __forceinline__ void gemm_body(
    const uint32_t* __restrict__ Ah, const uint32_t* __restrict__ Al,
    const uint32_t* __restrict__ Bh, const uint32_t* __restrict__ Bl,
    const float* __restrict__ bias, float* __restrict__ C,
    int headsplit, uint32_t* smu)
{
    const int N = EMB;
    const int tid  = threadIdx.x;
    const int wid  = tid >> 5;
    const int lane = tid & 31;
    const int gid  = lane >> 2;
    const int tig  = lane & 3;
    const int wm   = wid >> 1;
    const int wn   = wid & 1;
    const int row0 = blockIdx.y * 128;
    const int col0 = blockIdx.x * 128;

    float c[2][8][4];
#pragma unroll
    for (int mt = 0; mt < 2; mt++)
#pragma unroll
        for (int nt = 0; nt < 8; nt++)
#pragma unroll
            for (int i = 0; i < 4; i++) c[mt][nt][i] = 0.f;

    // A staging: thread -> row ar, positions apo..apo+3
    const int ar = tid >> 1, apo = (tid & 1) * 4;
    // B staging: thread -> kappa kb, col-pair nl2 (cols 2nl2, 2nl2+1, both deltas)
    const int kb = tid >> 6, nl2 = tid & 63;

    const uint32_t* Ahb = Ah + (size_t)(row0 + ar) * KPAIRS + apo;
    const uint32_t* Alb = Al + (size_t)(row0 + ar) * KPAIRS + apo;
    const uint4* Bh4 = (const uint4*)Bh;
    const uint4* Bl4 = (const uint4*)Bl;
    const size_t bbase = (size_t)kb * 512 + (col0 >> 1) + nl2;   // uint4 index; +slab*2048

    uint4 a_h = *(const uint4*)(Ahb);
    uint4 a_l = *(const uint4*)(Alb);
    uint4 b_h = Bh4[bbase];
    uint4 b_l = Bl4[bbase];

    *(uint4*)&SAh(0, ar, apo)     = a_h;
    *(uint4*)&SAl(0, ar, apo)     = a_l;
    *(uint4*)&SBh2(0, kb, nl2*4)  = b_h;
    *(uint4*)&SBl2(0, kb, nl2*4)  = b_l;
    __syncthreads();

    int cur = 0;
    for (int slab = 0; slab < 64; slab++) {
        const bool more = (slab + 1 < 64);
        if (more) {
            a_h = *(const uint4*)(Ahb + (slab + 1) * 8);
            a_l = *(const uint4*)(Alb + (slab + 1) * 8);
            b_h = Bh4[bbase + (size_t)(slab + 1) * 2048];
            b_l = Bl4[bbase + (size_t)(slab + 1) * 2048];
        }

        uint32_t ahi[2][4], alo[2][4];
#pragma unroll
        for (int mt = 0; mt < 2; mt++) {
            const int m0 = wm * 32 + mt * 16;
            uint2 v;
            v = *(const uint2*)&SAh(cur, m0 + gid,     2*tig); ahi[mt][0] = v.x; ahi[mt][2] = v.y;
            v = *(const uint2*)&SAh(cur, m0 + gid + 8, 2*tig); ahi[mt][1] = v.x; ahi[mt][3] = v.y;
            v = *(const uint2*)&SAl(cur, m0 + gid,     2*tig); alo[mt][0] = v.x; alo[mt][2] = v.y;
            v = *(const uint2*)&SAl(cur, m0 + gid + 8, 2*tig); alo[mt][1] = v.x; alo[mt][3] = v.y;
        }
#pragma unroll
        for (int nt = 0; nt < 8; nt++) {
            const int n0 = wn * 64 + nt * 8;
            uint32_t bh[2], bl[2];
            {
                uint2 v;
                v = *(const uint2*)&SBh2(cur, tig, (n0 + gid) * 2); bh[0] = v.x; bh[1] = v.y;
                v = *(const uint2*)&SBl2(cur, tig, (n0 + gid) * 2); bl[0] = v.x; bl[1] = v.y;
            }
#pragma unroll
            for (int mt = 0; mt < 2; mt++) {
                mma_bf16(c[mt][nt], ahi[mt], bh);
                mma_bf16(c[mt][nt], alo[mt], bh);
                mma_bf16(c[mt][nt], ahi[mt], bl);
            }
        }

        if (more) {
            const int nxt = cur ^ 1;
            *(uint4*)&SAh(nxt, ar, apo)    = a_h;
            *(uint4*)&SAl(nxt, ar, apo)    = a_l;
            *(uint4*)&SBh2(nxt, kb, nl2*4) = b_h;
            *(uint4*)&SBl2(nxt, kb, nl2*4) = b_l;
            __syncthreads();
            cur = nxt;
        }
    }

#pragma unroll
    for (int mt = 0; mt < 2; mt++) {
        const int m_lo = row0 + wm * 32 + mt * 16 + gid;
        const int m_hi = m_lo + 8;
#pragma unroll
        for (int nt = 0; nt < 8; nt++) {
            const int n = col0 + wn * 64 + nt * 8 + 2 * tig;
            const float b0 = bias[n], b1 = bias[n + 1];
            float v00 = c[mt][nt][0] + b0, v01 = c[mt][nt][1] + b1;
            float v10 = c[mt][nt][2] + b0, v11 = c[mt][nt][3] + b1;
            if (headsplit) {
                const int b_lo = m_lo / SEQ, s_lo = m_lo % SEQ;
                const int b_hi = m_hi / SEQ, s_hi = m_hi % SEQ;
                const int h = n / HDIM, d = n % HDIM;
                C[(((size_t)(b_lo*HEADS + h))*SEQ + s_lo)*HDIM + d    ] = v00;
                C[(((size_t)(b_lo*HEADS + h))*SEQ + s_lo)*HDIM + d + 1] = v01;
                C[(((size_t)(b_hi*HEADS + h))*SEQ + s_hi)*HDIM + d    ] = v10;
                C[(((size_t)(b_hi*HEADS + h))*SEQ + s_hi)*HDIM + d + 1] = v11;
            } else {
                C[(size_t)m_lo * N + n    ] = v00;
                C[(size_t)m_lo * N + n + 1] = v01;
                C[(size_t)m_hi * N + n    ] = v10;
                C[(size_t)m_hi * N + n + 1] = v11;
            }
        }
    }
}

__global__ __launch_bounds__(256)
void gemm_proj(const uint32_t* __restrict__ Ah, const uint32_t* __restrict__ Al,
               const uint32_t* __restrict__ Wh, const uint32_t* __restrict__ Wl,
               const float* __restrict__ b0, const float* __restrict__ b1,
               const float* __restrict__ b2,
               float* __restrict__ C0, float* __restrict__ C1, float* __restrict__ C2)
{
    extern __shared__ __align__(16) uint32_t smu[];
    const int z = blockIdx.z;
    const float* b = (z == 0) ? b0 : (z == 1) ? b1 : b2;
    float*       C = (z == 0) ? C0 : (z == 1) ? C1 : C2;
    gemm_body(Ah, Al, Wh + (size_t)z * KPAIRS * EMB, Wl + (size_t)z * KPAIRS * EMB,
              b, C, 1, smu);
}

__global__ __launch_bounds__(256)
void gemm_out(const uint32_t* __restrict__ Ah, const uint32_t* __restrict__ Al,
              const uint32_t* __restrict__ Wh, const uint32_t* __restrict__ Wl,
              const float* __restrict__ b, float* __restrict__ C)
{
    extern __shared__ __align__(16) uint32_t smu[];
    gemm_body(Ah, Al, Wh + (size_t)3 * KPAIRS * EMB, Wl + (size_t)3 * KPAIRS * EMB,
              b, C, 0, smu);
}

// ---------------------------------------------------------------------------
// Causal flash attention v7: v6 + paired P buffer (LDS.64), permuted ao epilogue.
// ---------------------------------------------------------------------------
#define QS(r,c)    sQ[(r)*68 + (c)]
#define KS_(r,c)   sK[(r)*68 + (c)]
#define VS_(r,c)   sV[(r)*72 + (c)]
#define SSW2(cc,j) sP[(cc)*40 + (j)]

#define ATTN_SMEM_FLOATS (128*68 + 32*68 + 32*72 + 4*32*40)
#define QSCALE (0.125f * 1.44269504088896340736f)   // 1/sqrt(D) * log2(e)

__global__ __launch_bounds__(128, 3)
void attn_tf32(const float* __restrict__ Q, const float* __restrict__ Kg,
               const float* __restrict__ Vg,
               uint32_t* __restrict__ AOh, uint32_t* __restrict__ AOl)
{
    extern __shared__ __align__(16) float smem[];
    float* sQ  = smem;                 // 128 x 68
    float* sK  = sQ + 128*68;          // 32 x 68
    float* sV  = sK + 32*68;           // 32 x 72
    float* sPb = sV + 32*72;           // 4 warps x (32 cc x 40)

    const int bh  = blockIdx.y;
    const int qt  = (gridDim.x - 1) - blockIdx.x;   // big-work blocks first
    const int tid = threadIdx.x;
    const int wid = tid >> 5;
    const int lane = tid & 31;
    const int gid = lane >> 2;
    const int tig = lane & 3;
    const int m0  = wid * 32;
    float* sP = sPb + wid * (32*40);

    const float* Qbase = Q + ((size_t)bh * SEQ + qt * 128) * HDIM;
    const float* Kbase = Kg + (size_t)bh * SEQ * HDIM;
    const float* Vbase = Vg + (size_t)bh * SEQ * HDIM;

    // stage Q (128x64), scaled by 1/sqrt(D)*log2e, cvt to tf32
    {
        const float* qr = Qbase + (size_t)tid * HDIM;
#pragma unroll
        for (int i = 0; i < 16; i++) {
            float4 v = *(const float4*)(qr + i * 4);
            v.x *= QSCALE; v.y *= QSCALE; v.z *= QSCALE; v.w *= QSCALE;
            *(float4*)&QS(tid, i * 4) = cvt4(v);
        }
    }
    __syncthreads();

    float o[2][8][4];
#pragma unroll
    for (int mt = 0; mt < 2; mt++)
#pragma unroll
        for (int nt = 0; nt < 8; nt++)
#pragma unroll
            for (int i = 0; i < 4; i++) o[mt][nt][i] = 0.f;
    float mrow[2][2] = {{-INFINITY,-INFINITY},{-INFINITY,-INFINITY}};
    float lrow[2][2] = {{0.f,0.f},{0.f,0.f}};

    const int qmax_warp = qt * 128 + m0 + 31;
    const int qmin_warp = qt * 128 + m0;
    const int nch = 4 * qt + 4;

    for (int ch = 0; ch < nch; ch++) {
        // stage K,V chunk (32x64), cvt to tf32
        {
            const int kr = tid >> 2, kc = (tid & 3) * 16;
            const float* kp = Kbase + (size_t)(ch * 32 + kr) * HDIM + kc;
            const float* vp = Vbase + (size_t)(ch * 32 + kr) * HDIM + kc;
#pragma unroll
            for (int i = 0; i < 4; i++) {
                *(float4*)&KS_(kr, kc + i * 4) = cvt4(*(const float4*)(kp + i * 4));
                *(float4*)&VS_(kr, kc + i * 4) = cvt4(*(const float4*)(vp + i * 4));
            }
        }
        __syncthreads();

        if (ch * 32 <= qmax_warp) {
            const bool needmask = (ch * 32 + 31 > qmin_warp);

            // ---- S = Q K^T : 32 rows x 32 keys per warp ----
            float s[2][4][4];
#pragma unroll
            for (int mt = 0; mt < 2; mt++)
#pragma unroll
                for (int nt = 0; nt < 4; nt++)
#pragma unroll
                    for (int i = 0; i < 4; i++) s[mt][nt][i] = 0.f;

#pragma unroll
            for (int ks = 0; ks < 8; ks++) {
                uint32_t a[2][4];
#pragma unroll
                for (int mt = 0; mt < 2; mt++) {
                    const int r0 = m0 + mt * 16;
                    a[mt][0] = __float_as_uint(QS(r0 + gid,     ks*8 + tig));
                    a[mt][1] = __float_as_uint(QS(r0 + gid + 8, ks*8 + tig));
                    a[mt][2] = __float_as_uint(QS(r0 + gid,     ks*8 + tig + 4));
                    a[mt][3] = __float_as_uint(QS(r0 + gid + 8, ks*8 + tig + 4));
                }
#pragma unroll
                for (int nt = 0; nt < 4; nt++) {
                    uint32_t b[2];
                    b[0] = __float_as_uint(KS_(nt*8 + gid, ks*8 + tig));
                    b[1] = __float_as_uint(KS_(nt*8 + gid, ks*8 + tig + 4));
                    mma_tf32(s[0][nt], a[0], b);
                    mma_tf32(s[1][nt], a[1], b);
                }
            }

            // ---- register online softmax (log2 domain) ----
#pragma unroll
            for (int mt = 0; mt < 2; mt++) {
#pragma unroll
                for (int half = 0; half < 2; half++) {
                    const int qrow = qt * 128 + m0 + mt * 16 + gid + half * 8;
                    const int cb   = ch * 32 + 2 * tig;
                    float mx = -INFINITY;
                    if (needmask) {
#pragma unroll
                        for (int nt = 0; nt < 4; nt++)
#pragma unroll
                            for (int ii = 0; ii < 2; ii++) {
                                const int cc = cb + nt * 8 + ii;
                                if (cc <= qrow)
                                    mx = fmaxf(mx, s[mt][nt][half * 2 + ii]);
                            }
                    } else {
#pragma unroll
                        for (int nt = 0; nt < 4; nt++)
#pragma unroll
                            for (int ii = 0; ii < 2; ii++)
                                mx = fmaxf(mx, s[mt][nt][half * 2 + ii]);
                    }
                    mx = fmaxf(mx, __shfl_xor_sync(0xffffffffu, mx, 1));
                    mx = fmaxf(mx, __shfl_xor_sync(0xffffffffu, mx, 2));
                    const float mold = mrow[mt][half];
                    const float mnew = fmaxf(mold, mx);
                    const float msafe = (mnew == -INFINITY) ? 0.f : mnew;
                    const float corr  = (mold == -INFINITY) ? 0.f : exp2f(mold - msafe);
                    float sum = 0.f;
                    if (needmask) {
#pragma unroll
                        for (int nt = 0; nt < 4; nt++)
#pragma unroll
                            for (int ii = 0; ii < 2; ii++) {
                                const int cc = cb + nt * 8 + ii;
                                float p = (cc <= qrow) ? exp2f(s[mt][nt][half*2+ii] - msafe) : 0.f;
                                s[mt][nt][half*2+ii] = p;
                                sum += p;
                            }
                    } else {
#pragma unroll
                        for (int nt = 0; nt < 4; nt++)
#pragma unroll
                            for (int ii = 0; ii < 2; ii++) {
                                float p = exp2f(s[mt][nt][half*2+ii] - msafe);
                                s[mt][nt][half*2+ii] = p;
                                sum += p;
                            }
                    }
                    sum += __shfl_xor_sync(0xffffffffu, sum, 1);
                    sum += __shfl_xor_sync(0xffffffffu, sum, 2);
                    lrow[mt][half] = lrow[mt][half] * corr + sum;
                    mrow[mt][half] = mnew;
#pragma unroll
                    for (int nt = 0; nt < 8; nt++) {
                        o[mt][nt][half*2+0] *= corr;
                        o[mt][nt][half*2+1] *= corr;
                    }
                }
            }

            // ---- write P (tf32-cvt'd), pair (rl, rl+8) adjacent -> STS.64 ----
#pragma unroll
            for (int mt = 0; mt < 2; mt++) {
                const int j = (mt * 8 + gid) * 2;
#pragma unroll
                for (int nt = 0; nt < 4; nt++) {
                    const int cc = nt * 8 + 2 * tig;
                    float2 v0, v1;
                    v0.x = __uint_as_float(tf32_rna(s[mt][nt][0]));
                    v0.y = __uint_as_float(tf32_rna(s[mt][nt][2]));
                    v1.x = __uint_as_float(tf32_rna(s[mt][nt][1]));
                    v1.y = __uint_as_float(tf32_rna(s[mt][nt][3]));
                    *(float2*)&SSW2(cc,     j) = v0;
                    *(float2*)&SSW2(cc + 1, j) = v1;
                }
            }
            __syncwarp();

            // ---- O += P V (P pairs via LDS.64) ----
#pragma unroll
            for (int ks = 0; ks < 4; ks++) {
                uint32_t p[2][4];
#pragma unroll
                for (int mt = 0; mt < 2; mt++) {
                    const int j = (mt * 8 + gid) * 2;
                    uint2 v;
                    v = *(const uint2*)&SSW2(ks*8 + tig,     j); p[mt][0] = v.x; p[mt][1] = v.y;
                    v = *(const uint2*)&SSW2(ks*8 + tig + 4, j); p[mt][2] = v.x; p[mt][3] = v.y;
                }
#pragma unroll
                for (int nt = 0; nt < 8; nt++) {
                    uint32_t v[2];
                    v[0] = __float_as_uint(VS_(ks*8 + tig,     nt*8 + gid));
                    v[1] = __float_as_uint(VS_(ks*8 + tig + 4, nt*8 + gid));
                    mma_tf32(o[0][nt], p[0], v);
                    mma_tf32(o[1][nt], p[1], v);
                }
            }
        }
        __syncthreads();
    }

    // epilogue: normalize, bf16-split, write permuted A-plane layout
    const int b = bh / HEADS, h = bh % HEADS;
#pragma unroll
    for (int mt = 0; mt < 2; mt++) {
#pragma unroll
        for (int half = 0; half < 2; half++) {
            const float inv = 1.f / lrow[mt][half];
            const int sg = qt * 128 + m0 + mt * 16 + gid + half * 8;
            const size_t rowbase = (size_t)(b * SEQ + sg) * KPAIRS;
#pragma unroll
            for (int nt = 0; nt < 8; nt++) {
                uint32_t hi, lo;
                bf16split2(o[mt][nt][half*2+0] * inv, o[mt][nt][half*2+1] * inv, hi, lo);
                // kp = h*32 + nt*4 + tig ; permuted pos = 2*tig + (nt&1), group = h*4 + (nt>>1)
                const size_t idx = rowbase + (size_t)(h * 4 + (nt >> 1)) * 8 + 2 * tig + (nt & 1);
                AOh[idx] = hi;
                AOl[idx] = lo;
            }
        }
    }
}

// ---------------------------------------------------------------------------
extern "C" void kernel_launch(void* const* d_in, const int* in_sizes, int n_in,
                              void* d_out, int out_size)
{
    const float* x  = (const float*)d_in[0];
    const float* Wq = (const float*)d_in[1];
    const float* bq = (const float*)d_in[2];
    const float* Wk = (const float*)d_in[3];
    const float* bk = (const float*)d_in[4];
    const float* Wv = (const float*)d_in[5];
    const float* bv = (const float*)d_in[6];
    const float* Wo = (const float*)d_in[7];
    const float* bo = (const float*)d_in[8];
    float* out = (float*)d_out;

    float *q_ptr, *k_ptr, *v_ptr;
    uint32_t *xh, *xl, *aoh, *aol, *wh, *wl;
    cudaGetSymbolAddress((void**)&q_ptr,  g_q);
    cudaGetSymbolAddress((void**)&k_ptr,  g_k);
    cudaGetSymbolAddress((void**)&v_ptr,  g_v);
    cudaGetSymbolAddress((void**)&xh,  g_xh);
    cudaGetSymbolAddress((void**)&xl,  g_xl);
    cudaGetSymbolAddress((void**)&aoh, g_aoh);
    cudaGetSymbolAddress((void**)&aol, g_aol);
    cudaGetSymbolAddress((void**)&wh,  g_wh);
    cudaGetSymbolAddress((void**)&wl,  g_wl);

    const int attn_smem = ATTN_SMEM_FLOATS * 4;
    static int attr_set = 0;
    if (!attr_set) {
        cudaFuncSetAttribute(attn_tf32,  cudaFuncAttributeMaxDynamicSharedMemorySize, attn_smem);
        cudaFuncSetAttribute(gemm_proj,  cudaFuncAttributeMaxDynamicSharedMemorySize, GEMM_SMEM_BYTES);
        cudaFuncSetAttribute(gemm_out,   cudaFuncAttributeMaxDynamicSharedMemorySize, GEMM_SMEM_BYTES);
        attr_set = 1;
    }

    // pre-split x and weights into fragment-friendly layouts
    {
        const int npairs = MROWS * KPAIRS;                 // 4.19M
        split_pairs<<<(npairs + 255) / 256, 256>>>(x, xh, xl, npairs);
        dim3 wgrid((KPAIRS * EMB) / 256, 4);               // (2048, 4)
        split_w<<<wgrid, 256>>>(Wq, Wk, Wv, Wo, wh, wl);
    }

    dim3 gblk(256);
    dim3 pgrid(EMB / 128, MROWS / 128, 3);   // (8, 64, 3)
    gemm_proj<<<pgrid, gblk, GEMM_SMEM_BYTES>>>(xh, xl, wh, wl, bq, bk, bv,
                                                q_ptr, k_ptr, v_ptr);

    dim3 agrid(SEQ / 128, BATCH * HEADS);    // (16, 64)
    attn_tf32<<<agrid, 128, attn_smem>>>(q_ptr, k_ptr, v_ptr, aoh, aol);

    dim3 ogrid(EMB / 128, MROWS / 128, 1);   // (8, 64)
    gemm_out<<<ogrid, gblk, GEMM_SMEM_BYTES>>>(aoh, aol, wh, wl, bo, out);
}